// round 2
// baseline (speedup 1.0000x reference)
#include <cuda_runtime.h>
#include <cuda_bf16.h>
#include <math.h>

// ---------------------------------------------------------------------------
// Problem constants (shapes fixed by the dataset)
// ---------------------------------------------------------------------------
#define MAXN 50000
#define DIN  128
#define H1   8          // heads layer 1
#define C1   128        // per-head dim layer 1
#define F1   (H1*C1)    // 1024
#define DOUT 128

// ---------------------------------------------------------------------------
// Scratch (no allocation allowed -> device globals)
// ---------------------------------------------------------------------------
__device__ float g_h1   [(size_t)MAXN * F1];   // x @ W1            [N,1024]
__device__ float g_agg  [(size_t)MAXN * F1];   // aggregated layer1 [N,1024]
__device__ float g_ssrc [(size_t)MAXN * H1];
__device__ float g_sdst [(size_t)MAXN * H1];
__device__ float g_emax [(size_t)MAXN * H1];
__device__ float g_den  [(size_t)MAXN * H1];
__device__ float g_h2   [(size_t)MAXN * DOUT]; // layer2 features
__device__ float g_ssrc2[(size_t)MAXN];
__device__ float g_sdst2[(size_t)MAXN];
__device__ float g_emax2[(size_t)MAXN];
__device__ float g_den2 [(size_t)MAXN];
__device__ float g_sum  [F1];
__device__ float g_sumsq[F1];
__device__ float g_mu   [F1];
__device__ float g_rstd [F1];

// ---------------------------------------------------------------------------
// Helpers
// ---------------------------------------------------------------------------
__device__ __forceinline__ void atomicMaxFloat(float* addr, float val) {
    if (val >= 0.0f) {
        atomicMax((int*)addr, __float_as_int(val));
    } else {
        atomicMin((unsigned int*)addr, __float_as_uint(val));
    }
}

__device__ __forceinline__ float leaky(float x) {
    return x > 0.0f ? x : 0.2f * x;
}

__global__ void fill_kernel(float* p, float v, int n) {
    int i = blockIdx.x * blockDim.x + threadIdx.x;
    if (i < n) p[i] = v;
}

// ---------------------------------------------------------------------------
// SGEMM: C[M,N] = A[M,K] @ B[K,N], row-major. BM=BN=64, BK=16, 4x4/thread.
// N,K multiples of 16/64 as used here; only M needs guards.
// ---------------------------------------------------------------------------
__global__ void sgemm_kernel(const float* __restrict__ A,
                             const float* __restrict__ B,
                             float* __restrict__ C,
                             int M, int K, int N) {
    const int BM = 64, BN = 64, BK = 16, TM = 4, TN = 4;
    __shared__ float As[BK][BM + 4];
    __shared__ float Bs[BK][BN + 4];

    const int tid = threadIdx.x;          // 256 threads
    const int bm  = blockIdx.y * BM;
    const int bn  = blockIdx.x * BN;
    const int tr  = (tid / 16) * TM;      // 0..60
    const int tc  = (tid % 16) * TN;      // 0..60

    float acc[TM][TN];
#pragma unroll
    for (int i = 0; i < TM; i++)
#pragma unroll
        for (int j = 0; j < TN; j++) acc[i][j] = 0.0f;

    for (int k0 = 0; k0 < K; k0 += BK) {
#pragma unroll
        for (int i = tid; i < BM * BK; i += 256) {
            int r = i / BK, c = i % BK;
            int gr = bm + r;
            As[c][r] = (gr < M) ? A[(size_t)gr * K + k0 + c] : 0.0f;
        }
#pragma unroll
        for (int i = tid; i < BK * BN; i += 256) {
            int r = i / BN, c = i % BN;
            Bs[r][c] = B[(size_t)(k0 + r) * N + bn + c];
        }
        __syncthreads();
#pragma unroll
        for (int kk = 0; kk < BK; kk++) {
            float a[TM], b[TN];
#pragma unroll
            for (int i = 0; i < TM; i++) a[i] = As[kk][tr + i];
#pragma unroll
            for (int j = 0; j < TN; j++) b[j] = Bs[kk][tc + j];
#pragma unroll
            for (int i = 0; i < TM; i++)
#pragma unroll
                for (int j = 0; j < TN; j++) acc[i][j] += a[i] * b[j];
        }
        __syncthreads();
    }

#pragma unroll
    for (int i = 0; i < TM; i++) {
        int gr = bm + tr + i;
        if (gr >= M) continue;
#pragma unroll
        for (int j = 0; j < TN; j++)
            C[(size_t)gr * N + bn + tc + j] = acc[i][j];
    }
}

// ---------------------------------------------------------------------------
// Layer-1 attention scores: one block per node, warp w handles head w.
// ---------------------------------------------------------------------------
__global__ void scores1_kernel(const float* __restrict__ h,
                               const float* __restrict__ a_src,
                               const float* __restrict__ a_dst,
                               float* __restrict__ s_src,
                               float* __restrict__ s_dst, int N) {
    int n = blockIdx.x;
    if (n >= N) return;
    int w = threadIdx.x >> 5;
    int lane = threadIdx.x & 31;
    const float4 hv = ((const float4*)(h + (size_t)n * F1 + w * C1))[lane];
    const float4 av = ((const float4*)(a_src + w * C1))[lane];
    const float4 bv = ((const float4*)(a_dst + w * C1))[lane];
    float ss = hv.x * av.x + hv.y * av.y + hv.z * av.z + hv.w * av.w;
    float sd = hv.x * bv.x + hv.y * bv.y + hv.z * bv.z + hv.w * bv.w;
#pragma unroll
    for (int o = 16; o > 0; o >>= 1) {
        ss += __shfl_down_sync(0xffffffff, ss, o);
        sd += __shfl_down_sync(0xffffffff, sd, o);
    }
    if (lane == 0) {
        s_src[n * H1 + w] = ss;
        s_dst[n * H1 + w] = sd;
    }
}

// Layer-2 scores (1 head, 128 dim): warp per node.
__global__ void scores2_kernel(const float* __restrict__ h,
                               const float* __restrict__ a_src,
                               const float* __restrict__ a_dst,
                               float* __restrict__ s_src,
                               float* __restrict__ s_dst, int N) {
    int warp = (blockIdx.x * blockDim.x + threadIdx.x) >> 5;
    int lane = threadIdx.x & 31;
    if (warp >= N) return;
    const float4 hv = ((const float4*)(h + (size_t)warp * DOUT))[lane];
    const float4 av = ((const float4*)a_src)[lane];
    const float4 bv = ((const float4*)a_dst)[lane];
    float ss = hv.x * av.x + hv.y * av.y + hv.z * av.z + hv.w * av.w;
    float sd = hv.x * bv.x + hv.y * bv.y + hv.z * bv.z + hv.w * bv.w;
#pragma unroll
    for (int o = 16; o > 0; o >>= 1) {
        ss += __shfl_down_sync(0xffffffff, ss, o);
        sd += __shfl_down_sync(0xffffffff, sd, o);
    }
    if (lane == 0) {
        s_src[warp] = ss;
        s_dst[warp] = sd;
    }
}

// ---------------------------------------------------------------------------
// Edge pass 1: segment max of leakyrelu(s_src[src]+s_dst[dst]) over dst.
// edge_index is int32: src = ei[e], dst = ei[E + e].
// ---------------------------------------------------------------------------
__global__ void edge_max_kernel(const int* __restrict__ ei,
                                const float* __restrict__ s_src,
                                const float* __restrict__ s_dst,
                                float* __restrict__ emax, int E, int H) {
    int i = blockIdx.x * blockDim.x + threadIdx.x;
    if (i >= E * H) return;
    int e = i / H, hd = i - e * H;
    int s = ei[e];
    int d = ei[E + e];
    float v = leaky(s_src[s * H + hd] + s_dst[d * H + hd]);
    atomicMaxFloat(&emax[d * H + hd], v);
}

// ---------------------------------------------------------------------------
// Edge pass 2 (layer 1): w = exp(e - emax[dst]); denom += w;
// agg[dst,h,:] += w * h1[src,h,:].  One warp per (edge,head).
// ---------------------------------------------------------------------------
__global__ void edge_agg1_kernel(const int* __restrict__ ei,
                                 const float* __restrict__ s_src,
                                 const float* __restrict__ s_dst,
                                 const float* __restrict__ emax,
                                 const float* __restrict__ h,
                                 float* __restrict__ den,
                                 float* __restrict__ agg, int E) {
    int warp = (blockIdx.x * blockDim.x + threadIdx.x) >> 5;
    int lane = threadIdx.x & 31;
    if (warp >= E * H1) return;
    int e = warp >> 3, hd = warp & 7;
    int s = ei[e];
    int d = ei[E + e];
    float v = leaky(s_src[s * H1 + hd] + s_dst[d * H1 + hd]);
    float w = expf(v - emax[d * H1 + hd]);
    if (lane == 0) atomicAdd(&den[d * H1 + hd], w);
    const float* hp = h + (size_t)s * F1 + hd * C1;
    float* ap = agg + (size_t)d * F1 + hd * C1;
#pragma unroll
    for (int i = 0; i < 4; i++) {
        int c = lane + 32 * i;
        atomicAdd(&ap[c], w * hp[c]);
    }
}

// Edge pass 2 (layer 2, single head): warp per edge, writes into d_out.
__global__ void edge_agg2_kernel(const int* __restrict__ ei,
                                 const float* __restrict__ s_src,
                                 const float* __restrict__ s_dst,
                                 const float* __restrict__ emax,
                                 const float* __restrict__ h,
                                 float* __restrict__ den,
                                 float* __restrict__ out, int E) {
    int warp = (blockIdx.x * blockDim.x + threadIdx.x) >> 5;
    int lane = threadIdx.x & 31;
    if (warp >= E) return;
    int s = ei[warp];
    int d = ei[E + warp];
    float v = leaky(s_src[s] + s_dst[d]);
    float w = expf(v - emax[d]);
    if (lane == 0) atomicAdd(&den[d], w);
    const float* hp = h + (size_t)s * DOUT;
    float* op = out + (size_t)d * DOUT;
#pragma unroll
    for (int i = 0; i < 4; i++) {
        int c = lane + 32 * i;
        atomicAdd(&op[c], w * hp[c]);
    }
}

// ---------------------------------------------------------------------------
// Normalize layer-1 aggregate by denom and add bias b1.
// ---------------------------------------------------------------------------
__global__ void div_bias1_kernel(float* __restrict__ agg,
                                 const float* __restrict__ den,
                                 const float* __restrict__ b1, int N) {
    int i = blockIdx.x * blockDim.x + threadIdx.x;
    int total = N * F1;
    if (i >= total) return;
    int n = i / F1;
    int c = i - n * F1;
    int hd = c >> 7;
    agg[i] = agg[i] / (den[n * H1 + hd] + 1e-16f) + b1[c];
}

// BN stats: each block handles a row-chunk; thread t covers channels 4t..4t+3.
__global__ void bn_stats_kernel(const float* __restrict__ h, int N) {
    int t = threadIdx.x;                       // 256
    int rows_per_block = (N + gridDim.x - 1) / gridDim.x;
    int r0 = blockIdx.x * rows_per_block;
    int r1 = min(N, r0 + rows_per_block);
    float4 s = make_float4(0, 0, 0, 0);
    float4 q = make_float4(0, 0, 0, 0);
    for (int r = r0; r < r1; r++) {
        float4 v = ((const float4*)(h + (size_t)r * F1))[t];
        s.x += v.x; s.y += v.y; s.z += v.z; s.w += v.w;
        q.x += v.x * v.x; q.y += v.y * v.y; q.z += v.z * v.z; q.w += v.w * v.w;
    }
    int c = t * 4;
    atomicAdd(&g_sum[c + 0], s.x); atomicAdd(&g_sum[c + 1], s.y);
    atomicAdd(&g_sum[c + 2], s.z); atomicAdd(&g_sum[c + 3], s.w);
    atomicAdd(&g_sumsq[c + 0], q.x); atomicAdd(&g_sumsq[c + 1], q.y);
    atomicAdd(&g_sumsq[c + 2], q.z); atomicAdd(&g_sumsq[c + 3], q.w);
}

__global__ void bn_finalize_kernel(int N) {
    int c = blockIdx.x * blockDim.x + threadIdx.x;
    if (c >= F1) return;
    float mu = g_sum[c] / (float)N;
    float var = g_sumsq[c] / (float)N - mu * mu;
    g_mu[c] = mu;
    g_rstd[c] = rsqrtf(var + 1e-5f);
}

__global__ void bn_apply_elu_kernel(float* __restrict__ h,
                                    const float* __restrict__ gamma,
                                    const float* __restrict__ beta, int N) {
    int i = blockIdx.x * blockDim.x + threadIdx.x;
    int total = N * F1;
    if (i >= total) return;
    int c = i & (F1 - 1);
    float v = h[i];
    v = gamma[c] * (v - g_mu[c]) * g_rstd[c] + beta[c];
    h[i] = v > 0.0f ? v : expm1f(v);
}

// Final: out = out/(den2+eps) + b2
__global__ void finalize_kernel(float* __restrict__ out,
                                const float* __restrict__ den,
                                const float* __restrict__ b2, int N) {
    int i = blockIdx.x * blockDim.x + threadIdx.x;
    int total = N * DOUT;
    if (i >= total) return;
    int n = i >> 7;
    int c = i & (DOUT - 1);
    out[i] = out[i] / (den[n] + 1e-16f) + b2[c];
}

// ---------------------------------------------------------------------------
// Host launcher
// ---------------------------------------------------------------------------
static inline int cdiv(int a, int b) { return (a + b - 1) / b; }

extern "C" void kernel_launch(void* const* d_in, const int* in_sizes, int n_in,
                              void* d_out, int out_size) {
    // --- identify inputs by element count (in signature order for ties) ---
    const float* x = nullptr;
    const int* ei = nullptr;          // int32 edge_index [2,E] (JAX x64 off)
    const float* W1 = nullptr; const float* W2 = nullptr;
    const float* v1024[5] = {nullptr, nullptr, nullptr, nullptr, nullptr};
    const float* v128[3]  = {nullptr, nullptr, nullptr};
    int n1024 = 0, n128 = 0, nW = 0;
    int N = MAXN, E = 150000;

    for (int i = 0; i < n_in; i++) {
        int sz = in_sizes[i];
        if (sz == MAXN * DIN)          { x = (const float*)d_in[i]; N = sz / DIN; }
        else if (sz == 300000)         { ei = (const int*)d_in[i]; E = sz / 2; }
        else if (sz == DIN * F1)       { if (nW == 0) W1 = (const float*)d_in[i];
                                         else W2 = (const float*)d_in[i]; nW++; }
        else if (sz == F1 && n1024 < 5) v1024[n1024++] = (const float*)d_in[i];
        else if (sz == DOUT && n128 < 3) v128[n128++] = (const float*)d_in[i];
    }
    const float* a_src1 = v1024[0];
    const float* a_dst1 = v1024[1];
    const float* b1     = v1024[2];
    const float* gamma  = v1024[3];
    const float* beta   = v1024[4];
    const float* a_src2 = v128[0];
    const float* a_dst2 = v128[1];
    const float* b2     = v128[2];
    float* out = (float*)d_out;

    // device-global scratch addresses
    float *h1, *agg, *ssrc, *sdst, *emax, *den, *h2, *ssrc2, *sdst2, *emax2,
          *den2, *bsum, *bsumsq;
    cudaGetSymbolAddress((void**)&h1, g_h1);
    cudaGetSymbolAddress((void**)&agg, g_agg);
    cudaGetSymbolAddress((void**)&ssrc, g_ssrc);
    cudaGetSymbolAddress((void**)&sdst, g_sdst);
    cudaGetSymbolAddress((void**)&emax, g_emax);
    cudaGetSymbolAddress((void**)&den, g_den);
    cudaGetSymbolAddress((void**)&h2, g_h2);
    cudaGetSymbolAddress((void**)&ssrc2, g_ssrc2);
    cudaGetSymbolAddress((void**)&sdst2, g_sdst2);
    cudaGetSymbolAddress((void**)&emax2, g_emax2);
    cudaGetSymbolAddress((void**)&den2, g_den2);
    cudaGetSymbolAddress((void**)&bsum, g_sum);
    cudaGetSymbolAddress((void**)&bsumsq, g_sumsq);

    const int T = 256;

    // ---- init scratch ----
    fill_kernel<<<cdiv(N * F1, T), T>>>(agg, 0.0f, N * F1);
    fill_kernel<<<cdiv(N * H1, T), T>>>(den, 0.0f, N * H1);
    fill_kernel<<<cdiv(N * H1, T), T>>>(emax, -INFINITY, N * H1);
    fill_kernel<<<cdiv(N, T), T>>>(den2, 0.0f, N);
    fill_kernel<<<cdiv(N, T), T>>>(emax2, -INFINITY, N);
    fill_kernel<<<cdiv(F1, T), T>>>(bsum, 0.0f, F1);
    fill_kernel<<<cdiv(F1, T), T>>>(bsumsq, 0.0f, F1);
    fill_kernel<<<cdiv(N * DOUT, T), T>>>(out, 0.0f, N * DOUT);

    // ---- layer 1 ----
    {
        dim3 grid(F1 / 64, cdiv(N, 64));
        sgemm_kernel<<<grid, 256>>>(x, W1, h1, N, DIN, F1);
    }
    scores1_kernel<<<N, 256>>>(h1, a_src1, a_dst1, ssrc, sdst, N);
    edge_max_kernel<<<cdiv(E * H1, T), T>>>(ei, ssrc, sdst, emax, E, H1);
    edge_agg1_kernel<<<cdiv(E * H1 * 32, T), T>>>(ei, ssrc, sdst, emax, h1,
                                                  den, agg, E);
    div_bias1_kernel<<<cdiv(N * F1, T), T>>>(agg, den, b1, N);

    // ---- batchnorm + elu ----
    bn_stats_kernel<<<200, 256>>>(agg, N);
    bn_finalize_kernel<<<cdiv(F1, T), T>>>(N);
    bn_apply_elu_kernel<<<cdiv(N * F1, T), T>>>(agg, gamma, beta, N);

    // ---- layer 2 ----
    {
        dim3 grid(DOUT / 64, cdiv(N, 64));
        sgemm_kernel<<<grid, 256>>>(agg, W2, h2, N, F1, DOUT);
    }
    scores2_kernel<<<cdiv(N * 32, T), T>>>(h2, a_src2, a_dst2, ssrc2, sdst2, N);
    edge_max_kernel<<<cdiv(E, T), T>>>(ei, ssrc2, sdst2, emax2, E, 1);
    edge_agg2_kernel<<<cdiv(E * 32, T), T>>>(ei, ssrc2, sdst2, emax2, h2,
                                             den2, out, E);
    finalize_kernel<<<cdiv(N * DOUT, T), T>>>(out, den2, b2, N);
}

// round 3
// speedup vs baseline: 1.2494x; 1.2494x over previous
#include <cuda_runtime.h>
#include <cuda_bf16.h>
#include <math.h>

#define MAXN 50000
#define DIN  128
#define H1   8
#define C1   128
#define F1   (H1*C1)    // 1024
#define DOUT 128

// ---------------------------------------------------------------------------
// Scratch
// ---------------------------------------------------------------------------
__device__ float g_h1   [(size_t)MAXN * F1];
__device__ float g_agg  [(size_t)MAXN * F1];
__device__ float g_ssrc [(size_t)MAXN * H1];
__device__ float g_sdst [(size_t)MAXN * H1];
__device__ float g_emax [(size_t)MAXN * H1];
__device__ float g_den  [(size_t)MAXN * H1];
__device__ float g_h2   [(size_t)MAXN * DOUT];
__device__ float g_ssrc2[(size_t)MAXN];
__device__ float g_sdst2[(size_t)MAXN];
__device__ float g_emax2[(size_t)MAXN];
__device__ float g_den2 [(size_t)MAXN];
__device__ float g_sum  [F1];
__device__ float g_sumsq[F1];
__device__ float g_mu   [F1];
__device__ float g_rstd [F1];

__device__ __forceinline__ void atomicMaxFloat(float* addr, float val) {
    if (val >= 0.0f) atomicMax((int*)addr, __float_as_int(val));
    else             atomicMin((unsigned int*)addr, __float_as_uint(val));
}
__device__ __forceinline__ float leaky(float x) { return x > 0.0f ? x : 0.2f * x; }

// zero the big aggregate buffer
__global__ void fill_agg_kernel(float* p, int n) {
    int i = blockIdx.x * blockDim.x + threadIdx.x;
    if (i < n) p[i] = 0.0f;
}
// zero/neg-inf all small per-node arrays in one launch
__global__ void fill_small_kernel(float* den, float* emax, float* den2,
                                  float* emax2, float* bsum, float* bsumsq,
                                  int N) {
    int i = blockIdx.x * blockDim.x + threadIdx.x;
    int nh = N * H1;
    if (i < nh) { den[i] = 0.0f; emax[i] = -INFINITY; }
    if (i < N)  { den2[i] = 0.0f; emax2[i] = -INFINITY; }
    if (i < F1) { bsum[i] = 0.0f; bsumsq[i] = 0.0f; }
}
__global__ void fill_out_kernel(float* p, int n) {
    int i = blockIdx.x * blockDim.x + threadIdx.x;
    if (i < n) p[i] = 0.0f;
}

// ---------------------------------------------------------------------------
// SGEMM: C[M,N] = A[M,K] @ B[K,N]. BM=BN=128, BK=8, 8x8 per thread, 256 thr.
// K % 8 == 0, N % 128 == 0; M guarded.
// ---------------------------------------------------------------------------
__global__ __launch_bounds__(256)
void sgemm_kernel(const float* __restrict__ A,
                  const float* __restrict__ B,
                  float* __restrict__ C,
                  int M, int K, int N) {
    const int BM = 128, BN = 128, BK = 8;
    __shared__ float As[BK][BM + 4];   // transposed A tile, padded
    __shared__ float Bs[BK][BN];

    const int tid = threadIdx.x;
    const int bm  = blockIdx.y * BM;
    const int bn  = blockIdx.x * BN;

    // loaders
    const int arow = tid >> 1;            // 0..127
    const int acol = (tid & 1) * 4;       // 0 or 4
    const int brow = tid >> 5;            // 0..7
    const int bcol = (tid & 31) * 4;      // 0..124

    // compute mapping: 16x16 thread grid of 8x8 micro-tiles
    const int trow = (tid >> 4) * 8;
    const int tcol = (tid & 15) * 8;

    float acc[8][8];
#pragma unroll
    for (int i = 0; i < 8; i++)
#pragma unroll
        for (int j = 0; j < 8; j++) acc[i][j] = 0.0f;

    for (int k0 = 0; k0 < K; k0 += BK) {
        // load A tile (128x8) as float4, store transposed
        {
            int gr = bm + arow;
            float4 v = make_float4(0.f, 0.f, 0.f, 0.f);
            if (gr < M) v = *(const float4*)&A[(size_t)gr * K + k0 + acol];
            As[acol + 0][arow] = v.x;
            As[acol + 1][arow] = v.y;
            As[acol + 2][arow] = v.z;
            As[acol + 3][arow] = v.w;
        }
        // load B tile (8x128) as float4
        {
            float4 v = *(const float4*)&B[(size_t)(k0 + brow) * N + bn + bcol];
            *(float4*)&Bs[brow][bcol] = v;
        }
        __syncthreads();

#pragma unroll
        for (int kk = 0; kk < BK; kk++) {
            float a[8], b[8];
            *(float4*)&a[0] = *(const float4*)&As[kk][trow];
            *(float4*)&a[4] = *(const float4*)&As[kk][trow + 4];
            *(float4*)&b[0] = *(const float4*)&Bs[kk][tcol];
            *(float4*)&b[4] = *(const float4*)&Bs[kk][tcol + 4];
#pragma unroll
            for (int i = 0; i < 8; i++)
#pragma unroll
                for (int j = 0; j < 8; j++) acc[i][j] += a[i] * b[j];
        }
        __syncthreads();
    }

#pragma unroll
    for (int i = 0; i < 8; i++) {
        int gr = bm + trow + i;
        if (gr >= M) continue;
        *(float4*)&C[(size_t)gr * N + bn + tcol]     = *(float4*)&acc[i][0];
        *(float4*)&C[(size_t)gr * N + bn + tcol + 4] = *(float4*)&acc[i][4];
    }
}

// ---------------------------------------------------------------------------
// Attention scores
// ---------------------------------------------------------------------------
__global__ void scores1_kernel(const float* __restrict__ h,
                               const float* __restrict__ a_src,
                               const float* __restrict__ a_dst,
                               float* __restrict__ s_src,
                               float* __restrict__ s_dst, int N) {
    int n = blockIdx.x;
    if (n >= N) return;
    int w = threadIdx.x >> 5;
    int lane = threadIdx.x & 31;
    const float4 hv = ((const float4*)(h + (size_t)n * F1 + w * C1))[lane];
    const float4 av = ((const float4*)(a_src + w * C1))[lane];
    const float4 bv = ((const float4*)(a_dst + w * C1))[lane];
    float ss = hv.x * av.x + hv.y * av.y + hv.z * av.z + hv.w * av.w;
    float sd = hv.x * bv.x + hv.y * bv.y + hv.z * bv.z + hv.w * bv.w;
#pragma unroll
    for (int o = 16; o > 0; o >>= 1) {
        ss += __shfl_down_sync(0xffffffff, ss, o);
        sd += __shfl_down_sync(0xffffffff, sd, o);
    }
    if (lane == 0) {
        s_src[n * H1 + w] = ss;
        s_dst[n * H1 + w] = sd;
    }
}

__global__ void scores2_kernel(const float* __restrict__ h,
                               const float* __restrict__ a_src,
                               const float* __restrict__ a_dst,
                               float* __restrict__ s_src,
                               float* __restrict__ s_dst, int N) {
    int warp = (blockIdx.x * blockDim.x + threadIdx.x) >> 5;
    int lane = threadIdx.x & 31;
    if (warp >= N) return;
    const float4 hv = ((const float4*)(h + (size_t)warp * DOUT))[lane];
    const float4 av = ((const float4*)a_src)[lane];
    const float4 bv = ((const float4*)a_dst)[lane];
    float ss = hv.x * av.x + hv.y * av.y + hv.z * av.z + hv.w * av.w;
    float sd = hv.x * bv.x + hv.y * bv.y + hv.z * bv.z + hv.w * bv.w;
#pragma unroll
    for (int o = 16; o > 0; o >>= 1) {
        ss += __shfl_down_sync(0xffffffff, ss, o);
        sd += __shfl_down_sync(0xffffffff, sd, o);
    }
    if (lane == 0) {
        s_src[warp] = ss;
        s_dst[warp] = sd;
    }
}

// ---------------------------------------------------------------------------
// Edge passes
// ---------------------------------------------------------------------------
__global__ void edge_max_kernel(const int* __restrict__ ei,
                                const float* __restrict__ s_src,
                                const float* __restrict__ s_dst,
                                float* __restrict__ emax, int E, int H) {
    int i = blockIdx.x * blockDim.x + threadIdx.x;
    if (i >= E * H) return;
    int e = i / H, hd = i - e * H;
    int s = ei[e];
    int d = ei[E + e];
    float v = leaky(s_src[s * H + hd] + s_dst[d * H + hd]);
    atomicMaxFloat(&emax[d * H + hd], v);
}

__global__ void edge_agg1_kernel(const int* __restrict__ ei,
                                 const float* __restrict__ s_src,
                                 const float* __restrict__ s_dst,
                                 const float* __restrict__ emax,
                                 const float* __restrict__ h,
                                 float* __restrict__ den,
                                 float* __restrict__ agg, int E) {
    int warp = (blockIdx.x * blockDim.x + threadIdx.x) >> 5;
    int lane = threadIdx.x & 31;
    if (warp >= E * H1) return;
    int e = warp >> 3, hd = warp & 7;
    int s = ei[e];
    int d = ei[E + e];
    float v = leaky(s_src[s * H1 + hd] + s_dst[d * H1 + hd]);
    float w = expf(v - emax[d * H1 + hd]);
    if (lane == 0) atomicAdd(&den[d * H1 + hd], w);
    const float* hp = h + (size_t)s * F1 + hd * C1;
    float* ap = agg + (size_t)d * F1 + hd * C1;
#pragma unroll
    for (int i = 0; i < 4; i++) {
        int c = lane + 32 * i;
        atomicAdd(&ap[c], w * hp[c]);
    }
}

__global__ void edge_agg2_kernel(const int* __restrict__ ei,
                                 const float* __restrict__ s_src,
                                 const float* __restrict__ s_dst,
                                 const float* __restrict__ emax,
                                 const float* __restrict__ h,
                                 float* __restrict__ den,
                                 float* __restrict__ out, int E) {
    int warp = (blockIdx.x * blockDim.x + threadIdx.x) >> 5;
    int lane = threadIdx.x & 31;
    if (warp >= E) return;
    int s = ei[warp];
    int d = ei[E + warp];
    float v = leaky(s_src[s] + s_dst[d]);
    float w = expf(v - emax[d]);
    if (lane == 0) atomicAdd(&den[d], w);
    const float* hp = h + (size_t)s * DOUT;
    float* op = out + (size_t)d * DOUT;
#pragma unroll
    for (int i = 0; i < 4; i++) {
        int c = lane + 32 * i;
        atomicAdd(&op[c], w * hp[c]);
    }
}

// ---------------------------------------------------------------------------
// BN (with div+bias folded in) + ELU
// ---------------------------------------------------------------------------
__global__ void bn_stats_kernel(const float* __restrict__ agg,
                                const float* __restrict__ den,
                                const float* __restrict__ b1, int N) {
    int t = threadIdx.x;                       // 256; channels 4t..4t+3
    int c = t * 4;
    int hd = c >> 7;
    float4 bb = *(const float4*)&b1[c];
    int rows_per_block = (N + gridDim.x - 1) / gridDim.x;
    int r0 = blockIdx.x * rows_per_block;
    int r1 = min(N, r0 + rows_per_block);
    float4 s = make_float4(0, 0, 0, 0);
    float4 q = make_float4(0, 0, 0, 0);
    for (int r = r0; r < r1; r++) {
        float inv = 1.0f / (den[r * H1 + hd] + 1e-16f);
        float4 v = ((const float4*)(agg + (size_t)r * F1))[t];
        v.x = v.x * inv + bb.x; v.y = v.y * inv + bb.y;
        v.z = v.z * inv + bb.z; v.w = v.w * inv + bb.w;
        s.x += v.x; s.y += v.y; s.z += v.z; s.w += v.w;
        q.x += v.x * v.x; q.y += v.y * v.y; q.z += v.z * v.z; q.w += v.w * v.w;
    }
    atomicAdd(&g_sum[c + 0], s.x); atomicAdd(&g_sum[c + 1], s.y);
    atomicAdd(&g_sum[c + 2], s.z); atomicAdd(&g_sum[c + 3], s.w);
    atomicAdd(&g_sumsq[c + 0], q.x); atomicAdd(&g_sumsq[c + 1], q.y);
    atomicAdd(&g_sumsq[c + 2], q.z); atomicAdd(&g_sumsq[c + 3], q.w);
}

__global__ void bn_finalize_kernel(int N) {
    int c = blockIdx.x * blockDim.x + threadIdx.x;
    if (c >= F1) return;
    float mu = g_sum[c] / (float)N;
    float var = g_sumsq[c] / (float)N - mu * mu;
    g_mu[c] = mu;
    g_rstd[c] = rsqrtf(var + 1e-5f);
}

__global__ void bn_apply_elu_kernel(float* __restrict__ agg,
                                    const float* __restrict__ den,
                                    const float* __restrict__ b1,
                                    const float* __restrict__ gamma,
                                    const float* __restrict__ beta, int N) {
    int i = blockIdx.x * blockDim.x + threadIdx.x;
    int total = N * F1;
    if (i >= total) return;
    int n = i >> 10;
    int c = i & (F1 - 1);
    int hd = c >> 7;
    float v = agg[i] / (den[n * H1 + hd] + 1e-16f) + b1[c];
    v = gamma[c] * (v - g_mu[c]) * g_rstd[c] + beta[c];
    agg[i] = v > 0.0f ? v : expm1f(v);
}

__global__ void finalize_kernel(float* __restrict__ out,
                                const float* __restrict__ den,
                                const float* __restrict__ b2, int N) {
    int i = blockIdx.x * blockDim.x + threadIdx.x;
    int total = N * DOUT;
    if (i >= total) return;
    int n = i >> 7;
    int c = i & (DOUT - 1);
    out[i] = out[i] / (den[n] + 1e-16f) + b2[c];
}

// ---------------------------------------------------------------------------
static inline int cdiv(int a, int b) { return (a + b - 1) / b; }

extern "C" void kernel_launch(void* const* d_in, const int* in_sizes, int n_in,
                              void* d_out, int out_size) {
    const float* x = nullptr;
    const int* ei = nullptr;
    const float* W1 = nullptr; const float* W2 = nullptr;
    const float* v1024[5] = {nullptr, nullptr, nullptr, nullptr, nullptr};
    const float* v128[3]  = {nullptr, nullptr, nullptr};
    int n1024 = 0, n128 = 0, nW = 0;
    int N = MAXN, E = 150000;

    for (int i = 0; i < n_in; i++) {
        int sz = in_sizes[i];
        if (sz == MAXN * DIN)          { x = (const float*)d_in[i]; N = sz / DIN; }
        else if (sz == 300000)         { ei = (const int*)d_in[i]; E = sz / 2; }
        else if (sz == DIN * F1)       { if (nW == 0) W1 = (const float*)d_in[i];
                                         else W2 = (const float*)d_in[i]; nW++; }
        else if (sz == F1 && n1024 < 5) v1024[n1024++] = (const float*)d_in[i];
        else if (sz == DOUT && n128 < 3) v128[n128++] = (const float*)d_in[i];
    }
    const float* a_src1 = v1024[0];
    const float* a_dst1 = v1024[1];
    const float* b1     = v1024[2];
    const float* gamma  = v1024[3];
    const float* beta   = v1024[4];
    const float* a_src2 = v128[0];
    const float* a_dst2 = v128[1];
    const float* b2     = v128[2];
    float* out = (float*)d_out;

    float *h1, *agg, *ssrc, *sdst, *emax, *den, *h2, *ssrc2, *sdst2, *emax2,
          *den2, *bsum, *bsumsq;
    cudaGetSymbolAddress((void**)&h1, g_h1);
    cudaGetSymbolAddress((void**)&agg, g_agg);
    cudaGetSymbolAddress((void**)&ssrc, g_ssrc);
    cudaGetSymbolAddress((void**)&sdst, g_sdst);
    cudaGetSymbolAddress((void**)&emax, g_emax);
    cudaGetSymbolAddress((void**)&den, g_den);
    cudaGetSymbolAddress((void**)&h2, g_h2);
    cudaGetSymbolAddress((void**)&ssrc2, g_ssrc2);
    cudaGetSymbolAddress((void**)&sdst2, g_sdst2);
    cudaGetSymbolAddress((void**)&emax2, g_emax2);
    cudaGetSymbolAddress((void**)&den2, g_den2);
    cudaGetSymbolAddress((void**)&bsum, g_sum);
    cudaGetSymbolAddress((void**)&bsumsq, g_sumsq);

    const int T = 256;

    // launch order chosen so ncu (-s 5 -c 1) profiles edge_agg1 (index 5)
    {   // 0: GEMM1 (x @ W1)
        dim3 grid(F1 / 128, cdiv(N, 128));
        sgemm_kernel<<<grid, 256>>>(x, W1, h1, N, DIN, F1);
    }
    // 1,2: scratch init
    fill_agg_kernel<<<cdiv(N * F1, T), T>>>(agg, N * F1);
    fill_small_kernel<<<cdiv(N * H1, T), T>>>(den, emax, den2, emax2,
                                              bsum, bsumsq, N);
    // 3: scores
    scores1_kernel<<<N, 256>>>(h1, a_src1, a_dst1, ssrc, sdst, N);
    // 4: segment max
    edge_max_kernel<<<cdiv(E * H1, T), T>>>(ei, ssrc, sdst, emax, E, H1);
    // 5: edge aggregation  <-- profiled launch
    edge_agg1_kernel<<<cdiv(E * H1 * 32, T), T>>>(ei, ssrc, sdst, emax, h1,
                                                  den, agg, E);
    // 6-8: BN (div+bias folded) + ELU
    bn_stats_kernel<<<200, 256>>>(agg, den, b1, N);
    bn_finalize_kernel<<<cdiv(F1, T), T>>>(N);
    bn_apply_elu_kernel<<<cdiv(N * F1, T), T>>>(agg, den, b1, gamma, beta, N);
    // 9: GEMM2
    {
        dim3 grid(DOUT / 128, cdiv(N, 128));
        sgemm_kernel<<<grid, 256>>>(agg, W2, h2, N, F1, DOUT);
    }
    // 10: zero output (accumulated by edge_agg2)
    fill_out_kernel<<<cdiv(N * DOUT, T), T>>>(out, N * DOUT);
    // 11-13: layer-2 attention
    scores2_kernel<<<cdiv(N * 32, T), T>>>(h2, a_src2, a_dst2, ssrc2, sdst2, N);
    edge_max_kernel<<<cdiv(E, T), T>>>(ei, ssrc2, sdst2, emax2, E, 1);
    edge_agg2_kernel<<<cdiv(E * 32, T), T>>>(ei, ssrc2, sdst2, emax2, h2,
                                             den2, out, E);
    // 14: final normalize + bias
    finalize_kernel<<<cdiv(N * DOUT, T), T>>>(out, den2, b2, N);
}

// round 4
// speedup vs baseline: 1.3684x; 1.0952x over previous
#include <cuda_runtime.h>
#include <cuda_bf16.h>
#include <math.h>
#include <stdint.h>

#define MAXN 50000
#define DIN  128
#define H1   8
#define C1   128
#define F1   (H1*C1)    // 1024
#define DOUT 128

// ---------------------------------------------------------------------------
// Scratch
// ---------------------------------------------------------------------------
__device__ float g_h1   [(size_t)MAXN * F1];
__device__ float g_agg  [(size_t)MAXN * F1];
__device__ float g_ssrc [(size_t)MAXN * H1];
__device__ float g_sdst [(size_t)MAXN * H1];
__device__ float g_emax [(size_t)MAXN * H1];
__device__ float g_den  [(size_t)MAXN * H1];
__device__ float g_h2   [(size_t)MAXN * DOUT];
__device__ float g_ssrc2[(size_t)MAXN];
__device__ float g_sdst2[(size_t)MAXN];
__device__ float g_emax2[(size_t)MAXN];
__device__ float g_den2 [(size_t)MAXN];
__device__ float g_sum  [F1];
__device__ float g_sumsq[F1];
__device__ float g_mu   [F1];
__device__ float g_rstd [F1];

__device__ __forceinline__ void atomicMaxFloat(float* addr, float val) {
    if (val >= 0.0f) atomicMax((int*)addr, __float_as_int(val));
    else             atomicMin((unsigned int*)addr, __float_as_uint(val));
}
__device__ __forceinline__ float leaky(float x) { return x > 0.0f ? x : 0.2f * x; }

__global__ void fill_agg_kernel(float* p, int n) {
    int i = blockIdx.x * blockDim.x + threadIdx.x;
    if (i < n) p[i] = 0.0f;
}
__global__ void fill_small_kernel(float* den, float* emax, float* den2,
                                  float* emax2, float* bsum, float* bsumsq,
                                  int N) {
    int i = blockIdx.x * blockDim.x + threadIdx.x;
    int nh = N * H1;
    if (i < nh) { den[i] = 0.0f; emax[i] = -INFINITY; }
    if (i < N)  { den2[i] = 0.0f; emax2[i] = -INFINITY; }
    if (i < F1) { bsum[i] = 0.0f; bsumsq[i] = 0.0f; }
}
__global__ void fill_out_kernel(float* p, int n) {
    int i = blockIdx.x * blockDim.x + threadIdx.x;
    if (i < n) p[i] = 0.0f;
}

// ---------------------------------------------------------------------------
// tf32x3 tensor-core GEMM: C[M,N] = A[M,K] @ B[K,N], fp32 in/out.
// Block 128x128, BK=16, 8 warps (each 64x32), m16n8k8 tf32 mma.
// Error-compensated: v = hi + lo (both tf32); D += Ah*Bh + Ah*Bl + Al*Bh.
// ---------------------------------------------------------------------------
__device__ __forceinline__ uint32_t f32_to_tf32(float x) {
    uint32_t r;
    asm("cvt.rna.tf32.f32 %0, %1;" : "=r"(r) : "f"(x));
    return r;
}

__device__ __forceinline__ void mma8(float* c, const uint32_t* a,
                                     const uint32_t* b) {
    asm volatile(
        "mma.sync.aligned.m16n8k8.row.col.f32.tf32.tf32.f32 "
        "{%0,%1,%2,%3}, {%4,%5,%6,%7}, {%8,%9}, {%0,%1,%2,%3};"
        : "+f"(c[0]), "+f"(c[1]), "+f"(c[2]), "+f"(c[3])
        : "r"(a[0]), "r"(a[1]), "r"(a[2]), "r"(a[3]),
          "r"(b[0]), "r"(b[1]));
}

#define BKG 16
#define PAD 4
__global__ __launch_bounds__(256)
void tf32_gemm_kernel(const float* __restrict__ A,
                      const float* __restrict__ B,
                      float* __restrict__ C,
                      int M, int K, int N) {
    const int BM = 128, BN = 128;
    __shared__ uint32_t Ahi[BKG][BM + PAD];
    __shared__ uint32_t Alo[BKG][BM + PAD];
    __shared__ uint32_t Bhi[BKG][BN + PAD];
    __shared__ uint32_t Blo[BKG][BN + PAD];

    const int tid  = threadIdx.x;
    const int wid  = tid >> 5;
    const int lane = tid & 31;
    const int bm = blockIdx.y * BM;
    const int bn = blockIdx.x * BN;
    const int wm = (wid >> 2) * 64;   // 0 or 64
    const int wn = (wid & 3) * 32;    // 0,32,64,96
    const int lg = lane >> 2;         // groupID 0..7
    const int lt = lane & 3;          // threadID-in-group 0..3

    float acc[4][4][4];
#pragma unroll
    for (int mt = 0; mt < 4; mt++)
#pragma unroll
        for (int nt = 0; nt < 4; nt++)
#pragma unroll
            for (int r = 0; r < 4; r++) acc[mt][nt][r] = 0.0f;

    for (int k0 = 0; k0 < K; k0 += BKG) {
        // load A tile 128x16 (2 float4 per thread), store transposed hi/lo
#pragma unroll
        for (int i = 0; i < 2; i++) {
            int lin = tid + i * 256;            // float4 index, 512 total
            int r   = lin >> 2;                 // row 0..127
            int c4  = (lin & 3) << 2;           // col 0,4,8,12
            int gr  = bm + r;
            float4 v = make_float4(0.f, 0.f, 0.f, 0.f);
            if (gr < M) v = *(const float4*)&A[(size_t)gr * K + k0 + c4];
            float vv[4] = {v.x, v.y, v.z, v.w};
#pragma unroll
            for (int j = 0; j < 4; j++) {
                uint32_t h = f32_to_tf32(vv[j]);
                float lo = vv[j] - __uint_as_float(h);
                Ahi[c4 + j][r] = h;
                Alo[c4 + j][r] = f32_to_tf32(lo);
            }
        }
        // load B tile 16x128
#pragma unroll
        for (int i = 0; i < 2; i++) {
            int lin = tid + i * 256;
            int r   = lin >> 5;                 // row 0..15
            int c4  = (lin & 31) << 2;          // col 0..124
            float4 v = *(const float4*)&B[(size_t)(k0 + r) * N + bn + c4];
            float vv[4] = {v.x, v.y, v.z, v.w};
#pragma unroll
            for (int j = 0; j < 4; j++) {
                uint32_t h = f32_to_tf32(vv[j]);
                float lo = vv[j] - __uint_as_float(h);
                Bhi[r][c4 + j] = h;
                Blo[r][c4 + j] = f32_to_tf32(lo);
            }
        }
        __syncthreads();

#pragma unroll
        for (int ks = 0; ks < BKG / 8; ks++) {
            const int kk = ks * 8;
            uint32_t ah[4][4], al[4][4];
#pragma unroll
            for (int mt = 0; mt < 4; mt++) {
                int r0 = wm + mt * 16 + lg;
                int c0 = kk + lt;
                ah[mt][0] = Ahi[c0][r0];       al[mt][0] = Alo[c0][r0];
                ah[mt][1] = Ahi[c0][r0 + 8];   al[mt][1] = Alo[c0][r0 + 8];
                ah[mt][2] = Ahi[c0 + 4][r0];   al[mt][2] = Alo[c0 + 4][r0];
                ah[mt][3] = Ahi[c0 + 4][r0 + 8]; al[mt][3] = Alo[c0 + 4][r0 + 8];
            }
            uint32_t bh[4][2], bl[4][2];
#pragma unroll
            for (int nt = 0; nt < 4; nt++) {
                int cc = wn + nt * 8 + lg;
                int r0 = kk + lt;
                bh[nt][0] = Bhi[r0][cc];     bh[nt][1] = Bhi[r0 + 4][cc];
                bl[nt][0] = Blo[r0][cc];     bl[nt][1] = Blo[r0 + 4][cc];
            }
#pragma unroll
            for (int mt = 0; mt < 4; mt++)
#pragma unroll
                for (int nt = 0; nt < 4; nt++) {
                    mma8(acc[mt][nt], ah[mt], bh[nt]);
                    mma8(acc[mt][nt], ah[mt], bl[nt]);
                    mma8(acc[mt][nt], al[mt], bh[nt]);
                }
        }
        __syncthreads();
    }

    // epilogue
#pragma unroll
    for (int mt = 0; mt < 4; mt++) {
#pragma unroll
        for (int half = 0; half < 2; half++) {
            int gr = bm + wm + mt * 16 + lg + half * 8;
            if (gr >= M) continue;
#pragma unroll
            for (int nt = 0; nt < 4; nt++) {
                int gc = bn + wn + nt * 8 + lt * 2;
                float2 v = make_float2(acc[mt][nt][half * 2],
                                       acc[mt][nt][half * 2 + 1]);
                *(float2*)&C[(size_t)gr * N + gc] = v;
            }
        }
    }
}

// ---------------------------------------------------------------------------
// Attention scores
// ---------------------------------------------------------------------------
__global__ void scores1_kernel(const float* __restrict__ h,
                               const float* __restrict__ a_src,
                               const float* __restrict__ a_dst,
                               float* __restrict__ s_src,
                               float* __restrict__ s_dst, int N) {
    int n = blockIdx.x;
    if (n >= N) return;
    int w = threadIdx.x >> 5;
    int lane = threadIdx.x & 31;
    const float4 hv = ((const float4*)(h + (size_t)n * F1 + w * C1))[lane];
    const float4 av = ((const float4*)(a_src + w * C1))[lane];
    const float4 bv = ((const float4*)(a_dst + w * C1))[lane];
    float ss = hv.x * av.x + hv.y * av.y + hv.z * av.z + hv.w * av.w;
    float sd = hv.x * bv.x + hv.y * bv.y + hv.z * bv.z + hv.w * bv.w;
#pragma unroll
    for (int o = 16; o > 0; o >>= 1) {
        ss += __shfl_down_sync(0xffffffff, ss, o);
        sd += __shfl_down_sync(0xffffffff, sd, o);
    }
    if (lane == 0) {
        s_src[n * H1 + w] = ss;
        s_dst[n * H1 + w] = sd;
    }
}

__global__ void scores2_kernel(const float* __restrict__ h,
                               const float* __restrict__ a_src,
                               const float* __restrict__ a_dst,
                               float* __restrict__ s_src,
                               float* __restrict__ s_dst, int N) {
    int warp = (blockIdx.x * blockDim.x + threadIdx.x) >> 5;
    int lane = threadIdx.x & 31;
    if (warp >= N) return;
    const float4 hv = ((const float4*)(h + (size_t)warp * DOUT))[lane];
    const float4 av = ((const float4*)a_src)[lane];
    const float4 bv = ((const float4*)a_dst)[lane];
    float ss = hv.x * av.x + hv.y * av.y + hv.z * av.z + hv.w * av.w;
    float sd = hv.x * bv.x + hv.y * bv.y + hv.z * bv.z + hv.w * bv.w;
#pragma unroll
    for (int o = 16; o > 0; o >>= 1) {
        ss += __shfl_down_sync(0xffffffff, ss, o);
        sd += __shfl_down_sync(0xffffffff, sd, o);
    }
    if (lane == 0) {
        s_src[warp] = ss;
        s_dst[warp] = sd;
    }
}

// ---------------------------------------------------------------------------
// Edge passes
// ---------------------------------------------------------------------------
__global__ void edge_max_kernel(const int* __restrict__ ei,
                                const float* __restrict__ s_src,
                                const float* __restrict__ s_dst,
                                float* __restrict__ emax, int E, int H) {
    int i = blockIdx.x * blockDim.x + threadIdx.x;
    if (i >= E * H) return;
    int e = i / H, hd = i - e * H;
    int s = ei[e];
    int d = ei[E + e];
    float v = leaky(s_src[s * H + hd] + s_dst[d * H + hd]);
    atomicMaxFloat(&emax[d * H + hd], v);
}

__global__ void edge_agg1_kernel(const int* __restrict__ ei,
                                 const float* __restrict__ s_src,
                                 const float* __restrict__ s_dst,
                                 const float* __restrict__ emax,
                                 const float* __restrict__ h,
                                 float* __restrict__ den,
                                 float* __restrict__ agg, int E) {
    int warp = (blockIdx.x * blockDim.x + threadIdx.x) >> 5;
    int lane = threadIdx.x & 31;
    if (warp >= E * H1) return;
    int e = warp >> 3, hd = warp & 7;
    int s = ei[e];
    int d = ei[E + e];
    float v = leaky(s_src[s * H1 + hd] + s_dst[d * H1 + hd]);
    float w = expf(v - emax[d * H1 + hd]);
    if (lane == 0) atomicAdd(&den[d * H1 + hd], w);
    const float* hp = h + (size_t)s * F1 + hd * C1;
    float* ap = agg + (size_t)d * F1 + hd * C1;
#pragma unroll
    for (int i = 0; i < 4; i++) {
        int c = lane + 32 * i;
        atomicAdd(&ap[c], w * hp[c]);
    }
}

__global__ void edge_agg2_kernel(const int* __restrict__ ei,
                                 const float* __restrict__ s_src,
                                 const float* __restrict__ s_dst,
                                 const float* __restrict__ emax,
                                 const float* __restrict__ h,
                                 float* __restrict__ den,
                                 float* __restrict__ out, int E) {
    int warp = (blockIdx.x * blockDim.x + threadIdx.x) >> 5;
    int lane = threadIdx.x & 31;
    if (warp >= E) return;
    int s = ei[warp];
    int d = ei[E + warp];
    float v = leaky(s_src[s] + s_dst[d]);
    float w = expf(v - emax[d]);
    if (lane == 0) atomicAdd(&den[d], w);
    const float* hp = h + (size_t)s * DOUT;
    float* op = out + (size_t)d * DOUT;
#pragma unroll
    for (int i = 0; i < 4; i++) {
        int c = lane + 32 * i;
        atomicAdd(&op[c], w * hp[c]);
    }
}

// ---------------------------------------------------------------------------
// BN (div+bias folded) + ELU
// ---------------------------------------------------------------------------
__global__ void bn_stats_kernel(const float* __restrict__ agg,
                                const float* __restrict__ den,
                                const float* __restrict__ b1, int N) {
    int t = threadIdx.x;
    int c = t * 4;
    int hd = c >> 7;
    float4 bb = *(const float4*)&b1[c];
    int rows_per_block = (N + gridDim.x - 1) / gridDim.x;
    int r0 = blockIdx.x * rows_per_block;
    int r1 = min(N, r0 + rows_per_block);
    float4 s = make_float4(0, 0, 0, 0);
    float4 q = make_float4(0, 0, 0, 0);
    for (int r = r0; r < r1; r++) {
        float inv = 1.0f / (den[r * H1 + hd] + 1e-16f);
        float4 v = ((const float4*)(agg + (size_t)r * F1))[t];
        v.x = v.x * inv + bb.x; v.y = v.y * inv + bb.y;
        v.z = v.z * inv + bb.z; v.w = v.w * inv + bb.w;
        s.x += v.x; s.y += v.y; s.z += v.z; s.w += v.w;
        q.x += v.x * v.x; q.y += v.y * v.y; q.z += v.z * v.z; q.w += v.w * v.w;
    }
    atomicAdd(&g_sum[c + 0], s.x); atomicAdd(&g_sum[c + 1], s.y);
    atomicAdd(&g_sum[c + 2], s.z); atomicAdd(&g_sum[c + 3], s.w);
    atomicAdd(&g_sumsq[c + 0], q.x); atomicAdd(&g_sumsq[c + 1], q.y);
    atomicAdd(&g_sumsq[c + 2], q.z); atomicAdd(&g_sumsq[c + 3], q.w);
}

__global__ void bn_finalize_kernel(int N) {
    int c = blockIdx.x * blockDim.x + threadIdx.x;
    if (c >= F1) return;
    float mu = g_sum[c] / (float)N;
    float var = g_sumsq[c] / (float)N - mu * mu;
    g_mu[c] = mu;
    g_rstd[c] = rsqrtf(var + 1e-5f);
}

__global__ void bn_apply_elu_kernel(float* __restrict__ agg,
                                    const float* __restrict__ den,
                                    const float* __restrict__ b1,
                                    const float* __restrict__ gamma,
                                    const float* __restrict__ beta, int N) {
    int i = blockIdx.x * blockDim.x + threadIdx.x;
    int total = N * F1;
    if (i >= total) return;
    int n = i >> 10;
    int c = i & (F1 - 1);
    int hd = c >> 7;
    float v = agg[i] / (den[n * H1 + hd] + 1e-16f) + b1[c];
    v = gamma[c] * (v - g_mu[c]) * g_rstd[c] + beta[c];
    agg[i] = v > 0.0f ? v : expm1f(v);
}

__global__ void finalize_kernel(float* __restrict__ out,
                                const float* __restrict__ den,
                                const float* __restrict__ b2, int N) {
    int i = blockIdx.x * blockDim.x + threadIdx.x;
    int total = N * DOUT;
    if (i >= total) return;
    int n = i >> 7;
    int c = i & (DOUT - 1);
    out[i] = out[i] / (den[n] + 1e-16f) + b2[c];
}

// ---------------------------------------------------------------------------
static inline int cdiv(int a, int b) { return (a + b - 1) / b; }

extern "C" void kernel_launch(void* const* d_in, const int* in_sizes, int n_in,
                              void* d_out, int out_size) {
    const float* x = nullptr;
    const int* ei = nullptr;
    const float* W1 = nullptr; const float* W2 = nullptr;
    const float* v1024[5] = {nullptr, nullptr, nullptr, nullptr, nullptr};
    const float* v128[3]  = {nullptr, nullptr, nullptr};
    int n1024 = 0, n128 = 0, nW = 0;
    int N = MAXN, E = 150000;

    for (int i = 0; i < n_in; i++) {
        int sz = in_sizes[i];
        if (sz == MAXN * DIN)          { x = (const float*)d_in[i]; N = sz / DIN; }
        else if (sz == 300000)         { ei = (const int*)d_in[i]; E = sz / 2; }
        else if (sz == DIN * F1)       { if (nW == 0) W1 = (const float*)d_in[i];
                                         else W2 = (const float*)d_in[i]; nW++; }
        else if (sz == F1 && n1024 < 5) v1024[n1024++] = (const float*)d_in[i];
        else if (sz == DOUT && n128 < 3) v128[n128++] = (const float*)d_in[i];
    }
    const float* a_src1 = v1024[0];
    const float* a_dst1 = v1024[1];
    const float* b1     = v1024[2];
    const float* gamma  = v1024[3];
    const float* beta   = v1024[4];
    const float* a_src2 = v128[0];
    const float* a_dst2 = v128[1];
    const float* b2     = v128[2];
    float* out = (float*)d_out;

    float *h1, *agg, *ssrc, *sdst, *emax, *den, *h2, *ssrc2, *sdst2, *emax2,
          *den2, *bsum, *bsumsq;
    cudaGetSymbolAddress((void**)&h1, g_h1);
    cudaGetSymbolAddress((void**)&agg, g_agg);
    cudaGetSymbolAddress((void**)&ssrc, g_ssrc);
    cudaGetSymbolAddress((void**)&sdst, g_sdst);
    cudaGetSymbolAddress((void**)&emax, g_emax);
    cudaGetSymbolAddress((void**)&den, g_den);
    cudaGetSymbolAddress((void**)&h2, g_h2);
    cudaGetSymbolAddress((void**)&ssrc2, g_ssrc2);
    cudaGetSymbolAddress((void**)&sdst2, g_sdst2);
    cudaGetSymbolAddress((void**)&emax2, g_emax2);
    cudaGetSymbolAddress((void**)&den2, g_den2);
    cudaGetSymbolAddress((void**)&bsum, g_sum);
    cudaGetSymbolAddress((void**)&bsumsq, g_sumsq);

    const int T = 256;

    // 0: GEMM1 (x @ W1) on tensor cores
    {
        dim3 grid(F1 / 128, cdiv(N, 128));
        tf32_gemm_kernel<<<grid, 256>>>(x, W1, h1, N, DIN, F1);
    }
    // 1,2: scratch init
    fill_agg_kernel<<<cdiv(N * F1, T), T>>>(agg, N * F1);
    fill_small_kernel<<<cdiv(N * H1, T), T>>>(den, emax, den2, emax2,
                                              bsum, bsumsq, N);
    // 3: scores
    scores1_kernel<<<N, 256>>>(h1, a_src1, a_dst1, ssrc, sdst, N);
    // 4: segment max
    edge_max_kernel<<<cdiv(E * H1, T), T>>>(ei, ssrc, sdst, emax, E, H1);
    // 5: edge aggregation
    edge_agg1_kernel<<<cdiv(E * H1 * 32, T), T>>>(ei, ssrc, sdst, emax, h1,
                                                  den, agg, E);
    // 6-8: BN + ELU
    bn_stats_kernel<<<200, 256>>>(agg, den, b1, N);
    bn_finalize_kernel<<<cdiv(F1, T), T>>>(N);
    bn_apply_elu_kernel<<<cdiv(N * F1, T), T>>>(agg, den, b1, gamma, beta, N);
    // 9: GEMM2 on tensor cores
    {
        dim3 grid(DOUT / 128, cdiv(N, 128));
        tf32_gemm_kernel<<<grid, 256>>>(agg, W2, h2, N, F1, DOUT);
    }
    // 10: zero output
    fill_out_kernel<<<cdiv(N * DOUT, T), T>>>(out, N * DOUT);
    // 11-13: layer-2 attention
    scores2_kernel<<<cdiv(N * 32, T), T>>>(h2, a_src2, a_dst2, ssrc2, sdst2, N);
    edge_max_kernel<<<cdiv(E, T), T>>>(ei, ssrc2, sdst2, emax2, E, 1);
    edge_agg2_kernel<<<cdiv(E * 32, T), T>>>(ei, ssrc2, sdst2, emax2, h2,
                                             den2, out, E);
    // 14: final normalize + bias
    finalize_kernel<<<cdiv(N * DOUT, T), T>>>(out, den2, b2, N);
}

// round 5
// speedup vs baseline: 1.7040x; 1.2452x over previous
#include <cuda_runtime.h>
#include <cuda_bf16.h>
#include <math.h>
#include <stdint.h>

#define MAXN 50000
#define MAXE 150000
#define DIN  128
#define H1   8
#define C1   128
#define F1   (H1*C1)    // 1024
#define DOUT 128

// ---------------------------------------------------------------------------
// Scratch
// ---------------------------------------------------------------------------
__device__ float g_h1   [(size_t)MAXN * F1];
__device__ float g_agg  [(size_t)MAXN * F1];
__device__ float g_h2   [(size_t)MAXN * DOUT];
__device__ float g_ssrc [(size_t)MAXN * H1];
__device__ float g_sdst [(size_t)MAXN * H1];
__device__ float g_ssrc2[(size_t)MAXN];
__device__ float g_sdst2[(size_t)MAXN];
__device__ float g_sum  [F1];
__device__ float g_sumsq[F1];
__device__ float g_mu   [F1];
__device__ float g_rstd [F1];
__device__ int   g_deg     [MAXN];
__device__ int   g_rowstart[MAXN + 1];
__device__ int   g_cursor  [MAXN];
__device__ int   g_eid     [MAXE];

__device__ __forceinline__ float leaky(float x) { return x > 0.0f ? x : 0.2f * x; }

// ---------------------------------------------------------------------------
// CSR build
// ---------------------------------------------------------------------------
__global__ void init_kernel(int* deg, float* bsum, float* bsumsq, int N) {
    int i = blockIdx.x * blockDim.x + threadIdx.x;
    if (i < N) deg[i] = 0;
    if (i < F1) { bsum[i] = 0.0f; bsumsq[i] = 0.0f; }
}

__global__ void count_kernel(const int* __restrict__ ei, int* __restrict__ deg,
                             int E) {
    int e = blockIdx.x * blockDim.x + threadIdx.x;
    if (e < E) atomicAdd(&deg[ei[E + e]], 1);
}

// single-block exclusive scan over deg -> rowstart (and cursor copy)
__global__ __launch_bounds__(1024)
void scan_kernel(const int* __restrict__ deg, int* __restrict__ rowstart,
                 int* __restrict__ cursor, int N) {
    const int T = 1024;
    int t = threadIdx.x;
    int chunk = (N + T - 1) / T;
    int s0 = t * chunk;
    int s1 = min(N, s0 + chunk);
    int sum = 0;
    for (int i = s0; i < s1; i++) sum += deg[i];

    __shared__ int wsum[32];
    int lane = t & 31, wid = t >> 5;
    int v = sum;
#pragma unroll
    for (int o = 1; o < 32; o <<= 1) {
        int u = __shfl_up_sync(0xffffffff, v, o);
        if (lane >= o) v += u;
    }
    if (lane == 31) wsum[wid] = v;
    __syncthreads();
    if (wid == 0) {
        int w = wsum[lane];
#pragma unroll
        for (int o = 1; o < 32; o <<= 1) {
            int u = __shfl_up_sync(0xffffffff, w, o);
            if (lane >= o) w += u;
        }
        wsum[lane] = w;
    }
    __syncthreads();
    int excl = v - sum + (wid > 0 ? wsum[wid - 1] : 0);

    int run = excl;
    for (int i = s0; i < s1; i++) {
        rowstart[i] = run;
        cursor[i] = run;
        run += deg[i];
    }
    if (s0 < N && s1 == N) rowstart[N] = run;
}

__global__ void scatter_kernel(const int* __restrict__ ei,
                               int* __restrict__ cursor,
                               int* __restrict__ eid, int E) {
    int e = blockIdx.x * blockDim.x + threadIdx.x;
    if (e >= E) return;
    int d = ei[E + e];
    int pos = atomicAdd(&cursor[d], 1);
    eid[pos] = e;
}

// ---------------------------------------------------------------------------
// tf32x3 tensor-core GEMM pieces
// ---------------------------------------------------------------------------
__device__ __forceinline__ uint32_t f32_to_tf32(float x) {
    uint32_t r;
    asm("cvt.rna.tf32.f32 %0, %1;" : "=r"(r) : "f"(x));
    return r;
}
__device__ __forceinline__ void mma8(float* c, const uint32_t* a,
                                     const uint32_t* b) {
    asm volatile(
        "mma.sync.aligned.m16n8k8.row.col.f32.tf32.tf32.f32 "
        "{%0,%1,%2,%3}, {%4,%5,%6,%7}, {%8,%9}, {%0,%1,%2,%3};"
        : "+f"(c[0]), "+f"(c[1]), "+f"(c[2]), "+f"(c[3])
        : "r"(a[0]), "r"(a[1]), "r"(a[2]), "r"(a[3]),
          "r"(b[0]), "r"(b[1]));
}

#define BKG 16
#define PAD 4

// BN_ELU = 0: plain A; BN_ELU = 1: A'(r,c) = elu(gamma*(A-mu)*rstd + beta)
template <int BN_ELU>
__global__ __launch_bounds__(256)
void tf32_gemm_kernel(const float* __restrict__ A,
                      const float* __restrict__ B,
                      float* __restrict__ C,
                      int M, int K, int N,
                      const float* __restrict__ gamma,
                      const float* __restrict__ beta,
                      const float* __restrict__ mu,
                      const float* __restrict__ rstd) {
    const int BM = 128, BN = 128;
    __shared__ uint32_t Ahi[BKG][BM + PAD];
    __shared__ uint32_t Alo[BKG][BM + PAD];
    __shared__ uint32_t Bhi[BKG][BN + PAD];
    __shared__ uint32_t Blo[BKG][BN + PAD];

    const int tid  = threadIdx.x;
    const int wid  = tid >> 5;
    const int lane = tid & 31;
    const int bm = blockIdx.y * BM;
    const int bn = blockIdx.x * BN;
    const int wm = (wid >> 2) * 64;
    const int wn = (wid & 3) * 32;
    const int lg = lane >> 2;
    const int lt = lane & 3;

    float acc[4][4][4];
#pragma unroll
    for (int mt = 0; mt < 4; mt++)
#pragma unroll
        for (int nt = 0; nt < 4; nt++)
#pragma unroll
            for (int r = 0; r < 4; r++) acc[mt][nt][r] = 0.0f;

    for (int k0 = 0; k0 < K; k0 += BKG) {
#pragma unroll
        for (int i = 0; i < 2; i++) {
            int lin = tid + i * 256;
            int r   = lin >> 2;
            int c4  = (lin & 3) << 2;
            int gr  = bm + r;
            float4 v = make_float4(0.f, 0.f, 0.f, 0.f);
            if (gr < M) {
                v = *(const float4*)&A[(size_t)gr * K + k0 + c4];
                if (BN_ELU) {
                    float vv[4] = {v.x, v.y, v.z, v.w};
#pragma unroll
                    for (int j = 0; j < 4; j++) {
                        int c = k0 + c4 + j;
                        float t = gamma[c] * (vv[j] - mu[c]) * rstd[c] + beta[c];
                        vv[j] = t > 0.0f ? t : expm1f(t);
                    }
                    v = make_float4(vv[0], vv[1], vv[2], vv[3]);
                }
            }
            float vv[4] = {v.x, v.y, v.z, v.w};
#pragma unroll
            for (int j = 0; j < 4; j++) {
                uint32_t h = f32_to_tf32(vv[j]);
                float lo = vv[j] - __uint_as_float(h);
                Ahi[c4 + j][r] = h;
                Alo[c4 + j][r] = f32_to_tf32(lo);
            }
        }
#pragma unroll
        for (int i = 0; i < 2; i++) {
            int lin = tid + i * 256;
            int r   = lin >> 5;
            int c4  = (lin & 31) << 2;
            float4 v = *(const float4*)&B[(size_t)(k0 + r) * N + bn + c4];
            float vv[4] = {v.x, v.y, v.z, v.w};
#pragma unroll
            for (int j = 0; j < 4; j++) {
                uint32_t h = f32_to_tf32(vv[j]);
                float lo = vv[j] - __uint_as_float(h);
                Bhi[r][c4 + j] = h;
                Blo[r][c4 + j] = f32_to_tf32(lo);
            }
        }
        __syncthreads();

#pragma unroll
        for (int ks = 0; ks < BKG / 8; ks++) {
            const int kk = ks * 8;
            uint32_t ah[4][4], al[4][4];
#pragma unroll
            for (int mt = 0; mt < 4; mt++) {
                int r0 = wm + mt * 16 + lg;
                int c0 = kk + lt;
                ah[mt][0] = Ahi[c0][r0];         al[mt][0] = Alo[c0][r0];
                ah[mt][1] = Ahi[c0][r0 + 8];     al[mt][1] = Alo[c0][r0 + 8];
                ah[mt][2] = Ahi[c0 + 4][r0];     al[mt][2] = Alo[c0 + 4][r0];
                ah[mt][3] = Ahi[c0 + 4][r0 + 8]; al[mt][3] = Alo[c0 + 4][r0 + 8];
            }
            uint32_t bh[4][2], bl[4][2];
#pragma unroll
            for (int nt = 0; nt < 4; nt++) {
                int cc = wn + nt * 8 + lg;
                int r0 = kk + lt;
                bh[nt][0] = Bhi[r0][cc];     bh[nt][1] = Bhi[r0 + 4][cc];
                bl[nt][0] = Blo[r0][cc];     bl[nt][1] = Blo[r0 + 4][cc];
            }
#pragma unroll
            for (int mt = 0; mt < 4; mt++)
#pragma unroll
                for (int nt = 0; nt < 4; nt++) {
                    mma8(acc[mt][nt], ah[mt], bh[nt]);
                    mma8(acc[mt][nt], ah[mt], bl[nt]);
                    mma8(acc[mt][nt], al[mt], bh[nt]);
                }
        }
        __syncthreads();
    }

#pragma unroll
    for (int mt = 0; mt < 4; mt++) {
#pragma unroll
        for (int half = 0; half < 2; half++) {
            int gr = bm + wm + mt * 16 + lg + half * 8;
            if (gr >= M) continue;
#pragma unroll
            for (int nt = 0; nt < 4; nt++) {
                int gc = bn + wn + nt * 8 + lt * 2;
                float2 v = make_float2(acc[mt][nt][half * 2],
                                       acc[mt][nt][half * 2 + 1]);
                *(float2*)&C[(size_t)gr * N + gc] = v;
            }
        }
    }
}

// ---------------------------------------------------------------------------
// Attention scores
// ---------------------------------------------------------------------------
__global__ void scores1_kernel(const float* __restrict__ h,
                               const float* __restrict__ a_src,
                               const float* __restrict__ a_dst,
                               float* __restrict__ s_src,
                               float* __restrict__ s_dst, int N) {
    int n = blockIdx.x;
    if (n >= N) return;
    int w = threadIdx.x >> 5;
    int lane = threadIdx.x & 31;
    const float4 hv = ((const float4*)(h + (size_t)n * F1 + w * C1))[lane];
    const float4 av = ((const float4*)(a_src + w * C1))[lane];
    const float4 bv = ((const float4*)(a_dst + w * C1))[lane];
    float ss = hv.x * av.x + hv.y * av.y + hv.z * av.z + hv.w * av.w;
    float sd = hv.x * bv.x + hv.y * bv.y + hv.z * bv.z + hv.w * bv.w;
#pragma unroll
    for (int o = 16; o > 0; o >>= 1) {
        ss += __shfl_down_sync(0xffffffff, ss, o);
        sd += __shfl_down_sync(0xffffffff, sd, o);
    }
    if (lane == 0) {
        s_src[n * H1 + w] = ss;
        s_dst[n * H1 + w] = sd;
    }
}

__global__ void scores2_kernel(const float* __restrict__ h,
                               const float* __restrict__ a_src,
                               const float* __restrict__ a_dst,
                               float* __restrict__ s_src,
                               float* __restrict__ s_dst, int N) {
    int warp = (blockIdx.x * blockDim.x + threadIdx.x) >> 5;
    int lane = threadIdx.x & 31;
    if (warp >= N) return;
    const float4 hv = ((const float4*)(h + (size_t)warp * DOUT))[lane];
    const float4 av = ((const float4*)a_src)[lane];
    const float4 bv = ((const float4*)a_dst)[lane];
    float ss = hv.x * av.x + hv.y * av.y + hv.z * av.z + hv.w * av.w;
    float sd = hv.x * bv.x + hv.y * bv.y + hv.z * bv.z + hv.w * bv.w;
#pragma unroll
    for (int o = 16; o > 0; o >>= 1) {
        ss += __shfl_down_sync(0xffffffff, ss, o);
        sd += __shfl_down_sync(0xffffffff, sd, o);
    }
    if (lane == 0) {
        s_src[warp] = ss;
        s_dst[warp] = sd;
    }
}

// ---------------------------------------------------------------------------
// Gather aggregation (no atomics): block per node, warp per head.
// agg[n,hd,:] = sum_e w_e * h[src_e,hd,:] / (sum_e w_e + eps)
// ---------------------------------------------------------------------------
__global__ __launch_bounds__(256)
void gather_agg1_kernel(const int* __restrict__ ei,
                        const int* __restrict__ rowstart,
                        const int* __restrict__ eid,
                        const float* __restrict__ ssrc,
                        const float* __restrict__ sdst,
                        const float* __restrict__ h,
                        float* __restrict__ agg, int E, int N) {
    int n = blockIdx.x;
    if (n >= N) return;
    int hd = threadIdx.x >> 5;
    int lane = threadIdx.x & 31;
    int r0 = rowstart[n], r1 = rowstart[n + 1];
    float sd = sdst[n * H1 + hd];

    float vmax = -INFINITY;
    for (int j = r0 + lane; j < r1; j += 32) {
        int e = eid[j];
        int s = ei[e];
        vmax = fmaxf(vmax, leaky(ssrc[s * H1 + hd] + sd));
    }
#pragma unroll
    for (int o = 16; o > 0; o >>= 1)
        vmax = fmaxf(vmax, __shfl_xor_sync(0xffffffff, vmax, o));

    float acc0 = 0, acc1 = 0, acc2 = 0, acc3 = 0, den = 0;
    for (int j = r0; j < r1; j++) {
        int e = eid[j];
        int s = ei[e];
        float v = leaky(ssrc[s * H1 + hd] + sd);
        float w = expf(v - vmax);
        den += w;
        const float* hp = h + (size_t)s * F1 + hd * C1;
        acc0 += w * hp[lane];
        acc1 += w * hp[lane + 32];
        acc2 += w * hp[lane + 64];
        acc3 += w * hp[lane + 96];
    }
    float inv = 1.0f / (den + 1e-16f);
    float* ap = agg + (size_t)n * F1 + hd * C1;
    ap[lane]      = acc0 * inv;
    ap[lane + 32] = acc1 * inv;
    ap[lane + 64] = acc2 * inv;
    ap[lane + 96] = acc3 * inv;
}

// Layer-2 gather: warp per node, writes final output (+b2) directly.
__global__ void gather_out2_kernel(const int* __restrict__ ei,
                                   const int* __restrict__ rowstart,
                                   const int* __restrict__ eid,
                                   const float* __restrict__ ssrc,
                                   const float* __restrict__ sdst,
                                   const float* __restrict__ h,
                                   const float* __restrict__ b2,
                                   float* __restrict__ out, int E, int N) {
    int n = (blockIdx.x * blockDim.x + threadIdx.x) >> 5;
    int lane = threadIdx.x & 31;
    if (n >= N) return;
    int r0 = rowstart[n], r1 = rowstart[n + 1];
    float sd = sdst[n];

    float vmax = -INFINITY;
    for (int j = r0 + lane; j < r1; j += 32) {
        int e = eid[j];
        int s = ei[e];
        vmax = fmaxf(vmax, leaky(ssrc[s] + sd));
    }
#pragma unroll
    for (int o = 16; o > 0; o >>= 1)
        vmax = fmaxf(vmax, __shfl_xor_sync(0xffffffff, vmax, o));

    float acc0 = 0, acc1 = 0, acc2 = 0, acc3 = 0, den = 0;
    for (int j = r0; j < r1; j++) {
        int e = eid[j];
        int s = ei[e];
        float v = leaky(ssrc[s] + sd);
        float w = expf(v - vmax);
        den += w;
        const float* hp = h + (size_t)s * DOUT;
        acc0 += w * hp[lane];
        acc1 += w * hp[lane + 32];
        acc2 += w * hp[lane + 64];
        acc3 += w * hp[lane + 96];
    }
    float inv = 1.0f / (den + 1e-16f);
    float* op = out + (size_t)n * DOUT;
    op[lane]      = acc0 * inv + b2[lane];
    op[lane + 32] = acc1 * inv + b2[lane + 32];
    op[lane + 64] = acc2 * inv + b2[lane + 64];
    op[lane + 96] = acc3 * inv + b2[lane + 96];
}

// ---------------------------------------------------------------------------
// BN stats (b1 cancels in BatchNorm, so plain moments of agg)
// ---------------------------------------------------------------------------
__global__ void bn_stats_kernel(const float* __restrict__ agg, int N) {
    int t = threadIdx.x;
    int c = t * 4;
    int rows_per_block = (N + gridDim.x - 1) / gridDim.x;
    int r0 = blockIdx.x * rows_per_block;
    int r1 = min(N, r0 + rows_per_block);
    float4 s = make_float4(0, 0, 0, 0);
    float4 q = make_float4(0, 0, 0, 0);
    for (int r = r0; r < r1; r++) {
        float4 v = ((const float4*)(agg + (size_t)r * F1))[t];
        s.x += v.x; s.y += v.y; s.z += v.z; s.w += v.w;
        q.x += v.x * v.x; q.y += v.y * v.y; q.z += v.z * v.z; q.w += v.w * v.w;
    }
    atomicAdd(&g_sum[c + 0], s.x); atomicAdd(&g_sum[c + 1], s.y);
    atomicAdd(&g_sum[c + 2], s.z); atomicAdd(&g_sum[c + 3], s.w);
    atomicAdd(&g_sumsq[c + 0], q.x); atomicAdd(&g_sumsq[c + 1], q.y);
    atomicAdd(&g_sumsq[c + 2], q.z); atomicAdd(&g_sumsq[c + 3], q.w);
}

__global__ void bn_finalize_kernel(int N) {
    int c = blockIdx.x * blockDim.x + threadIdx.x;
    if (c >= F1) return;
    float mu = g_sum[c] / (float)N;
    float var = g_sumsq[c] / (float)N - mu * mu;
    g_mu[c] = mu;
    g_rstd[c] = rsqrtf(var + 1e-5f);
}

// ---------------------------------------------------------------------------
static inline int cdiv(int a, int b) { return (a + b - 1) / b; }

extern "C" void kernel_launch(void* const* d_in, const int* in_sizes, int n_in,
                              void* d_out, int out_size) {
    const float* x = nullptr;
    const int* ei = nullptr;
    const float* W1 = nullptr; const float* W2 = nullptr;
    const float* v1024[5] = {nullptr, nullptr, nullptr, nullptr, nullptr};
    const float* v128[3]  = {nullptr, nullptr, nullptr};
    int n1024 = 0, n128 = 0, nW = 0;
    int N = MAXN, E = MAXE;

    for (int i = 0; i < n_in; i++) {
        int sz = in_sizes[i];
        if (sz == MAXN * DIN)          { x = (const float*)d_in[i]; N = sz / DIN; }
        else if (sz == 2 * MAXE)       { ei = (const int*)d_in[i]; E = sz / 2; }
        else if (sz == DIN * F1)       { if (nW == 0) W1 = (const float*)d_in[i];
                                         else W2 = (const float*)d_in[i]; nW++; }
        else if (sz == F1 && n1024 < 5) v1024[n1024++] = (const float*)d_in[i];
        else if (sz == DOUT && n128 < 3) v128[n128++] = (const float*)d_in[i];
    }
    const float* a_src1 = v1024[0];
    const float* a_dst1 = v1024[1];
    // v1024[2] = b1 : cancels inside BatchNorm -> unused
    const float* gamma  = v1024[3];
    const float* beta   = v1024[4];
    const float* a_src2 = v128[0];
    const float* a_dst2 = v128[1];
    const float* b2     = v128[2];
    float* out = (float*)d_out;

    float *h1, *agg, *h2, *ssrc, *sdst, *ssrc2, *sdst2, *bsum, *bsumsq,
          *mu, *rstd;
    int *deg, *rowstart, *cursor, *eid;
    cudaGetSymbolAddress((void**)&h1, g_h1);
    cudaGetSymbolAddress((void**)&agg, g_agg);
    cudaGetSymbolAddress((void**)&h2, g_h2);
    cudaGetSymbolAddress((void**)&ssrc, g_ssrc);
    cudaGetSymbolAddress((void**)&sdst, g_sdst);
    cudaGetSymbolAddress((void**)&ssrc2, g_ssrc2);
    cudaGetSymbolAddress((void**)&sdst2, g_sdst2);
    cudaGetSymbolAddress((void**)&bsum, g_sum);
    cudaGetSymbolAddress((void**)&bsumsq, g_sumsq);
    cudaGetSymbolAddress((void**)&mu, g_mu);
    cudaGetSymbolAddress((void**)&rstd, g_rstd);
    cudaGetSymbolAddress((void**)&deg, g_deg);
    cudaGetSymbolAddress((void**)&rowstart, g_rowstart);
    cudaGetSymbolAddress((void**)&cursor, g_cursor);
    cudaGetSymbolAddress((void**)&eid, g_eid);

    const int T = 256;

    // 0: GEMM1 (x @ W1)
    {
        dim3 grid(F1 / 128, cdiv(N, 128));
        tf32_gemm_kernel<0><<<grid, 256>>>(x, W1, h1, N, DIN, F1,
                                           nullptr, nullptr, nullptr, nullptr);
    }
    // 1-4: CSR build + stats zero
    init_kernel<<<cdiv(N, T), T>>>(deg, bsum, bsumsq, N);
    count_kernel<<<cdiv(E, T), T>>>(ei, deg, E);
    scan_kernel<<<1, 1024>>>(deg, rowstart, cursor, N);
    scatter_kernel<<<cdiv(E, T), T>>>(ei, cursor, eid, E);
    // 5: scores
    scores1_kernel<<<N, 256>>>(h1, a_src1, a_dst1, ssrc, sdst, N);
    // 6: gather aggregation (atomic-free)
    gather_agg1_kernel<<<N, 256>>>(ei, rowstart, eid, ssrc, sdst, h1, agg, E, N);
    // 7,8: BN stats
    bn_stats_kernel<<<200, 256>>>(agg, N);
    bn_finalize_kernel<<<cdiv(F1, T), T>>>(N);
    // 9: GEMM2 with BN+ELU fused into A loads
    {
        dim3 grid(DOUT / 128, cdiv(N, 128));
        tf32_gemm_kernel<1><<<grid, 256>>>(agg, W2, h2, N, F1, DOUT,
                                           gamma, beta, mu, rstd);
    }
    // 10: layer-2 scores
    scores2_kernel<<<cdiv(N * 32, T), T>>>(h2, a_src2, a_dst2, ssrc2, sdst2, N);
    // 11: layer-2 gather -> final output
    gather_out2_kernel<<<cdiv(N * 32, T), T>>>(ei, rowstart, eid, ssrc2, sdst2,
                                               h2, b2, out, E, N);
}